// round 1
// baseline (speedup 1.0000x reference)
#include <cuda_runtime.h>
#include <cuda_bf16.h>
#include <cstdint>

#define HH 768
#define WW 768
#define HW (768*768)
#define IP 769                 // integral image pitch (769x769 per channel)
#define IPP (769*769)

// ---------------- scratch (device globals: allocation-free) ----------------
__device__ float  g_feat1[32u * HW];           // conv1 output (75.5 MB)
__device__ double g_integ[64ull * IPP];        // conv2 output + integral image (303 MB)

// ---------------- f32x2 packed-FMA helpers (sm_103a) ----------------
__device__ __forceinline__ unsigned long long pk2(float lo, float hi) {
    unsigned long long r;
    asm("mov.b64 %0, {%1, %2};" : "=l"(r) : "r"(__float_as_uint(lo)), "r"(__float_as_uint(hi)));
    return r;
}
__device__ __forceinline__ void upk2(unsigned long long d, float& lo, float& hi) {
    unsigned int a, b;
    asm("mov.b64 {%0, %1}, %2;" : "=r"(a), "=r"(b) : "l"(d));
    lo = __uint_as_float(a); hi = __uint_as_float(b);
}
__device__ __forceinline__ unsigned long long ffma2(unsigned long long a, unsigned long long b,
                                                    unsigned long long c) {
    unsigned long long d;
    asm("fma.rn.f32x2 %0, %1, %2, %3;" : "=l"(d) : "l"(a), "l"(b), "l"(c));
    return d;
}

// ---------------- conv1: 3->32, 3x3, pad 1, fused bias+relu+bn1 ----------------
__global__ __launch_bounds__(256) void conv1_k(
    const float* __restrict__ img, const float* __restrict__ w,
    const float* __restrict__ bias, const float* __restrict__ gg,
    const float* __restrict__ bb, const float* __restrict__ mm,
    const float* __restrict__ vv)
{
    __shared__ __align__(16) float s_in[3][18][18];
    __shared__ __align__(16) float s_w[27 * 32];
    __shared__ float s_scale[32], s_shift[32], s_bias[32];

    const int tx = threadIdx.x, ty = threadIdx.y;
    const int tid = ty * 16 + tx;

    // weights: w[o][c][kh][kw] flat = o*27 + r  ->  s_w[r*32 + o]
    for (int i = tid; i < 864; i += 256) {
        int o = i / 27, r = i % 27;
        s_w[r * 32 + o] = w[i];
    }
    if (tid < 32) {
        float sc = gg[tid] * rsqrtf(vv[tid] + 1e-5f);
        s_scale[tid] = sc;
        s_shift[tid] = bb[tid] - mm[tid] * sc;
        s_bias[tid]  = bias[tid];
    }
    const int bx0 = blockIdx.x * 16 - 1, by0 = blockIdx.y * 16 - 1;
    for (int i = tid; i < 3 * 324; i += 256) {
        int c = i / 324, r = i % 324, yy = r / 18, xx = r % 18;
        int gy = by0 + yy, gx = bx0 + xx;
        float val = (gy >= 0 && gy < HH && gx >= 0 && gx < WW)
                        ? img[c * HW + gy * WW + gx] : 0.f;
        s_in[c][yy][xx] = val;
    }
    __syncthreads();

    float acc[32];
    #pragma unroll
    for (int o = 0; o < 32; o++) acc[o] = s_bias[o];

    #pragma unroll 1
    for (int c = 0; c < 3; c++) {
        #pragma unroll
        for (int t = 0; t < 9; t++) {
            float vr = s_in[c][ty + t / 3][tx + t % 3];
            const float4* wp = (const float4*)&s_w[(c * 9 + t) * 32];
            #pragma unroll
            for (int q = 0; q < 8; q++) {
                float4 ww = wp[q];
                acc[4*q+0] = fmaf(vr, ww.x, acc[4*q+0]);
                acc[4*q+1] = fmaf(vr, ww.y, acc[4*q+1]);
                acc[4*q+2] = fmaf(vr, ww.z, acc[4*q+2]);
                acc[4*q+3] = fmaf(vr, ww.w, acc[4*q+3]);
            }
        }
    }

    const int y = blockIdx.y * 16 + ty, x = blockIdx.x * 16 + tx;
    #pragma unroll
    for (int o = 0; o < 32; o++) {
        float r = fmaxf(acc[o], 0.f) * s_scale[o] + s_shift[o];
        g_feat1[(size_t)o * HW + y * WW + x] = r;
    }
}

// ---------------- conv2: 32->64, 3x3, pad 1, fused bias+relu+bn2 ----------------
// Writes directly into g_integ interior at [c][y+1][x+1] (as double).
__global__ __launch_bounds__(256) void conv2_k(
    const float* __restrict__ w, const float* __restrict__ bias,
    const float* __restrict__ gg, const float* __restrict__ bb,
    const float* __restrict__ mm, const float* __restrict__ vv)
{
    __shared__ __align__(16) float s_in[8][18][18];
    __shared__ __align__(16) float s_w[8 * 9 * 64];
    __shared__ float s_scale[64], s_shift[64];

    const int tx = threadIdx.x, ty = threadIdx.y;
    const int tid = ty * 16 + tx;

    if (tid < 64) {
        float sc = gg[tid] * rsqrtf(vv[tid] + 1e-5f);
        s_scale[tid] = sc;
        s_shift[tid] = bb[tid] - mm[tid] * sc;
    }

    unsigned long long acc[32];
    #pragma unroll
    for (int k = 0; k < 32; k++) acc[k] = pk2(bias[2*k], bias[2*k+1]);

    const int bx0 = blockIdx.x * 16 - 1, by0 = blockIdx.y * 16 - 1;

    #pragma unroll 1
    for (int cc = 0; cc < 4; cc++) {
        __syncthreads();
        // input chunk: channels [cc*8, cc*8+8)
        for (int i = tid; i < 8 * 324; i += 256) {
            int ci = i / 324, r = i % 324, yy = r / 18, xx = r % 18;
            int gy = by0 + yy, gx = bx0 + xx;
            float val = (gy >= 0 && gy < HH && gx >= 0 && gx < WW)
                            ? g_feat1[(size_t)(cc * 8 + ci) * HW + gy * WW + gx] : 0.f;
            s_in[ci][yy][xx] = val;
        }
        // weight chunk: w[o][ic][t] flat = o*288 + cc*72 + r, r = ci*9+t
        for (int i = tid; i < 4608; i += 256) {
            int r = i >> 6, o = i & 63;
            s_w[i] = w[o * 288 + cc * 72 + r];
        }
        __syncthreads();

        #pragma unroll 1
        for (int ci = 0; ci < 8; ci++) {
            float vreg[9];
            #pragma unroll
            for (int t = 0; t < 9; t++) vreg[t] = s_in[ci][ty + t / 3][tx + t % 3];
            #pragma unroll
            for (int t = 0; t < 9; t++) {
                unsigned long long v2 = pk2(vreg[t], vreg[t]);
                const ulonglong2* wp = (const ulonglong2*)&s_w[(ci * 9 + t) * 64];
                #pragma unroll
                for (int k2 = 0; k2 < 16; k2++) {
                    ulonglong2 q = wp[k2];
                    acc[2*k2+0] = ffma2(v2, q.x, acc[2*k2+0]);
                    acc[2*k2+1] = ffma2(v2, q.y, acc[2*k2+1]);
                }
            }
        }
    }

    const int y = blockIdx.y * 16 + ty, x = blockIdx.x * 16 + tx;
    const size_t base = (size_t)(y + 1) * IP + (x + 1);
    #pragma unroll
    for (int k = 0; k < 32; k++) {
        float lo, hi;
        upk2(acc[k], lo, hi);
        float r0 = fmaxf(lo, 0.f) * s_scale[2*k]   + s_shift[2*k];
        float r1 = fmaxf(hi, 0.f) * s_scale[2*k+1] + s_shift[2*k+1];
        g_integ[(size_t)(2*k)   * IPP + base] = (double)r0;
        g_integ[(size_t)(2*k+1) * IPP + base] = (double)r1;
    }
}

// ---------------- zero integral-image borders (row 0 / col 0 of each channel) ----------------
__global__ void zborder_k() {
    int i = blockIdx.x * 256 + threadIdx.x;
    if (i >= 64 * IP * 2) return;
    if (i < 64 * IP) {
        int c = i / IP, k = i % IP;
        g_integ[(size_t)c * IPP + k] = 0.0;             // row 0
    } else {
        i -= 64 * IP;
        int c = i / IP, k = i % IP;
        g_integ[(size_t)c * IPP + (size_t)k * IP] = 0.0; // col 0
    }
}

// ---------------- row-wise inclusive scan (x direction), fp64 ----------------
// One warp per row; each lane handles 24 consecutive elements (768 = 32*24).
__global__ __launch_bounds__(256) void rowscan_k() {
    const int warp = threadIdx.x >> 5, lane = threadIdx.x & 31;
    const int row = blockIdx.x * 8 + warp;      // 0 .. 64*768-1
    const int c = row / HH, y = row % HH + 1;
    double* p = g_integ + (size_t)c * IPP + (size_t)y * IP + 1;

    double v[24];
    #pragma unroll
    for (int i = 0; i < 24; i++) v[i] = p[lane * 24 + i];
    #pragma unroll
    for (int i = 1; i < 24; i++) v[i] += v[i - 1];
    double tot = v[23];
    double sc = tot;
    #pragma unroll
    for (int d = 1; d < 32; d <<= 1) {
        double n = __shfl_up_sync(0xffffffffu, sc, d);
        if (lane >= d) sc += n;
    }
    double excl = __shfl_up_sync(0xffffffffu, sc, 1);
    if (lane == 0) excl = 0.0;
    #pragma unroll
    for (int i = 0; i < 24; i++) p[lane * 24 + i] = v[i] + excl;
}

// ---------------- column-wise inclusive scan (y direction), fp64 ----------------
__global__ __launch_bounds__(256) void colscan_k() {
    int idx = blockIdx.x * 256 + threadIdx.x;
    if (idx >= 64 * WW) return;
    int c = idx / WW, x = idx % WW + 1;
    double* p = g_integ + (size_t)c * IPP + x;
    double s = 0.0;
    #pragma unroll 4
    for (int y = 1; y <= HH; y++) {
        s += p[(size_t)y * IP];
        p[(size_t)y * IP] = s;
    }
}

// ---------------- ROI pool (5x5 via integral image) + FC1(relu) + FC2 ----------------
__global__ __launch_bounds__(128) void roi_fc_k(
    const int* __restrict__ boxes,
    const float* __restrict__ fc1w, const float* __restrict__ fc1b,
    const float* __restrict__ fc2w, const float* __restrict__ fc2b,
    float* __restrict__ out)
{
    __shared__ float s_pool[1600];
    __shared__ float s_h1[128];
    __shared__ int sy0[5], sy1[5], sx0[5], sx1[5];

    const int b = blockIdx.x, tid = threadIdx.x;
    if (tid < 5) {
        int xmin = boxes[b*4+0], ymin = boxes[b*4+1];
        int xmax = boxes[b*4+2], ymax = boxes[b*4+3];
        int bh = ymax - ymin, bw = xmax - xmin;
        sy0[tid] = ymin + tid * bh / 5;
        sy1[tid] = ymin + ((tid + 1) * bh + 4) / 5;
        sx0[tid] = xmin + tid * bw / 5;
        sx1[tid] = xmin + ((tid + 1) * bw + 4) / 5;
    }
    __syncthreads();

    for (int idx = tid; idx < 1600; idx += 128) {
        int c = idx / 25, r = idx % 25, i = r / 5, j = r % 5;
        const double* I = g_integ + (size_t)c * IPP;
        double s = I[(size_t)sy1[i] * IP + sx1[j]] - I[(size_t)sy0[i] * IP + sx1[j]]
                 - I[(size_t)sy1[i] * IP + sx0[j]] + I[(size_t)sy0[i] * IP + sx0[j]];
        double area = (double)((sy1[i] - sy0[i]) * (sx1[j] - sx0[j]));
        s_pool[idx] = (float)(s / area);
    }
    __syncthreads();

    const int warp = tid >> 5, lane = tid & 31;
    // fc1: warp-cooperative dot products (coalesced weight reads)
    for (int o = warp; o < 128; o += 4) {
        const float* wr = fc1w + o * 1600;
        float sum = 0.f;
        for (int k = lane; k < 1600; k += 32) sum = fmaf(wr[k], s_pool[k], sum);
        #pragma unroll
        for (int d = 16; d; d >>= 1) sum += __shfl_down_sync(0xffffffffu, sum, d);
        if (lane == 0) s_h1[o] = fmaxf(sum + fc1b[o], 0.f);
    }
    __syncthreads();

    // fc2: warp o computes output o
    {
        int o = warp;
        float sum = 0.f;
        #pragma unroll
        for (int k = lane; k < 128; k += 32) sum = fmaf(fc2w[o * 128 + k], s_h1[k], sum);
        #pragma unroll
        for (int d = 16; d; d >>= 1) sum += __shfl_down_sync(0xffffffffu, sum, d);
        if (lane == 0) out[b * 4 + o] = sum + fc2b[o];
    }
}

// ---------------- launch ----------------
extern "C" void kernel_launch(void* const* d_in, const int* in_sizes, int n_in,
                              void* d_out, int out_size)
{
    const float* image = (const float*)d_in[0];
    const int*   boxes = (const int*)  d_in[1];
    const float* c1w = (const float*)d_in[2];
    const float* c1b = (const float*)d_in[3];
    const float* b1g = (const float*)d_in[4];
    const float* b1b = (const float*)d_in[5];
    const float* b1m = (const float*)d_in[6];
    const float* b1v = (const float*)d_in[7];
    const float* c2w = (const float*)d_in[8];
    const float* c2b = (const float*)d_in[9];
    const float* b2g = (const float*)d_in[10];
    const float* b2b = (const float*)d_in[11];
    const float* b2m = (const float*)d_in[12];
    const float* b2v = (const float*)d_in[13];
    const float* f1w = (const float*)d_in[14];
    const float* f1b = (const float*)d_in[15];
    const float* f2w = (const float*)d_in[16];
    const float* f2b = (const float*)d_in[17];
    float* out = (float*)d_out;

    dim3 blk(16, 16), grd(48, 48);
    conv1_k<<<grd, blk>>>(image, c1w, c1b, b1g, b1b, b1m, b1v);
    zborder_k<<<(64 * IP * 2 + 255) / 256, 256>>>();
    conv2_k<<<grd, blk>>>(c2w, c2b, b2g, b2b, b2m, b2v);
    rowscan_k<<<64 * HH / 8, 256>>>();
    colscan_k<<<(64 * WW + 255) / 256, 256>>>();
    roi_fc_k<<<512, 128>>>(boxes, f1w, f1b, f2w, f2b, out);
}